// round 9
// baseline (speedup 1.0000x reference)
#include <cuda_runtime.h>

#define L_SAMPLES 360000
#define N_BATCH   32
#define T_FRAMES  750
#define KSIZE     1003
#define NCHUNK    22500   // number of 16-sample leaf tiles per row

// Recursion sizes for the ReduceWindowRewriter structure (base 16):
// scan(22500): pad 22512 -> 1407 tiles ; scan(1407): pad 1408 -> 88 tiles ;
// scan(88): pad 96 -> 6 tiles ; scan(6): naive sequential fold.
#define L1N 1407
#define L1P 1408
#define L2N 88
#define L2P 96
#define L3N 6

// Leaf config (R, R): both constant divides strength-reduced to multiplies
// by the correctly-rounded fp32 reciprocals.
#define RCP_SR   (1.0f / 24000.0f)
#define RCP_FS   (1.0f / 480.0f)

// Scratch (static device arrays — no runtime allocation)
__device__ float g_E4[N_BATCH][NCHUNK];        // leaf-tile sums S0 (sequential folds)
__device__ float g_P [N_BATCH][NCHUNK];        // inclusive scan of S0 (block prefixes)
__device__ float g_imp[N_BATCH][L_SAMPLES];    // impulse train

// ---------------------------------------------------------------------------
// Bitwise emulation of the reference elementwise math.
// ---------------------------------------------------------------------------
__device__ __forceinline__ float f0_interp(const float* __restrict__ f0row, int i) {
    float x = __fmul_rn(__fadd_rn((float)i, 0.5f), RCP_FS);
    x = __fadd_rn(x, -0.5f);
    x = fminf(fmaxf(x, 0.0f), 749.0f);     // jnp.clip
    float fi0 = floorf(x);
    int i0 = (int)fi0;
    int i1 = i0 + 1; if (i1 > 749) i1 = 749;
    float w = __fadd_rn(x, -fi0);
    float a = __fmul_rn(f0row[i0], __fadd_rn(1.0f, -w));
    float b = __fmul_rn(f0row[i1], w);
    return __fadd_rn(a, b);
}

__device__ __forceinline__ float vval(const float* __restrict__ f0row, int i) {
    return __fmul_rn(-f0_interp(f0row, i), RCP_SR);   // -f0_up * (1/24000)
}

// jnp.mod(x, 1.0): trunc rem, then +1.0 if (rem != 0 && rem < 0)
__device__ __forceinline__ float jmod1(float r) {
    float t = fmodf(r, 1.0f);
    if (t != 0.0f && t < 0.0f) t = __fadd_rn(t, 1.0f);
    return t;
}

// Naive reduce-window emitter semantics (the rewriter's inner scan stays a
// width-16 reduce_window): each output = sequential left fold from init 0 in
// increasing window order. Running accumulator is bitwise identical because
// left folds share prefixes.
__device__ __forceinline__ void seq16(const float* __restrict__ in, float* __restrict__ out) {
    float acc = 0.0f;
#pragma unroll
    for (int i = 0; i < 16; i++) { acc = __fadd_rn(acc, in[i]); out[i] = acc; }
}

// ---------------------------------------------------------------------------
// K1: per-tile (16 samples) SEQUENTIAL sums -> S0 (= inner_scan[:,15]).
// ---------------------------------------------------------------------------
__global__ void k1_up(const float* __restrict__ f0) {
    __shared__ float sf0[T_FRAMES];
    int row = blockIdx.y;
    for (int j = threadIdx.x; j < T_FRAMES; j += blockDim.x)
        sf0[j] = f0[row * T_FRAMES + j];
    __syncthreads();

    int c = blockIdx.x * blockDim.x + threadIdx.x;
    if (c >= NCHUNK) return;
    int base = c * 16;

    float acc = 0.0f;
#pragma unroll
    for (int j = 0; j < 16; j++) acc = __fadd_rn(acc, vval(sf0, base + j));
    g_E4[row][c] = acc;
}

// ---------------------------------------------------------------------------
// K2: ReduceWindowRewriter recursion on S0 (length 22500) -> g_P.
//   pad->22512, seq16 tiles (1407 sums) -> pad->1408, seq16 (88 sums)
//   -> pad->96, seq16 (6 sums) -> sequential fold -> exclusive down-combines.
// ---------------------------------------------------------------------------
__global__ void k2_mid() {
    extern __shared__ float sm[];
    float* s0 = sm;                 // 22512 (W0 in place)
    float* s1 = sm + 22512;         // 1408  (W1 in place)
    float* s2 = s1 + L1P;           // 96    (W2 in place)
    float* s3 = s2 + L2P;           // 6
    int row = blockIdx.x;

    for (int i = threadIdx.x; i < 22512; i += blockDim.x)
        s0[i] = (i < NCHUNK) ? g_E4[row][i] : 0.0f;
    __syncthreads();

    // level: scan(22500) tiles (sequential in-tile)
    for (int b = threadIdx.x; b < L1N; b += blockDim.x) {
        float w[16];
        seq16(s0 + 16*b, w);
#pragma unroll
        for (int i = 0; i < 16; i++) s0[16*b + i] = w[i];
        s1[b] = w[15];
    }
    if (threadIdx.x == 0) s1[L1N] = 0.0f;   // pad 1407 -> 1408
    __syncthreads();

    // level: scan(1407) tiles
    for (int b = threadIdx.x; b < L2N; b += blockDim.x) {
        float w[16];
        seq16(s1 + 16*b, w);
#pragma unroll
        for (int i = 0; i < 16; i++) s1[16*b + i] = w[i];
        s2[b] = w[15];
    }
    for (int i = L2N + threadIdx.x; i < L2P; i += blockDim.x) s2[i] = 0.0f;  // pad 88 -> 96
    __syncthreads();

    // level: scan(88) tiles
    for (int b = threadIdx.x; b < L3N; b += blockDim.x) {
        float w[16];
        seq16(s2 + 16*b, w);
#pragma unroll
        for (int i = 0; i < 16; i++) s2[16*b + i] = w[i];
        s3[b] = w[15];
    }
    __syncthreads();

    // scan(6): naive reduce_window = sequential left fold from init 0
    if (threadIdx.x == 0) {
        float acc = 0.0f;
        for (int i = 0; i < L3N; i++) { acc = __fadd_rn(acc, s3[i]); s3[i] = acc; }
    }
    __syncthreads();

    // down-combine: scan88[j] = W2[j] + excl(scan6)
    for (int j = threadIdx.x; j < L2N; j += blockDim.x) {
        int b = j >> 4;
        s2[j] = __fadd_rn(s2[j], b ? s3[b-1] : 0.0f);
    }
    __syncthreads();
    // scan1407[j] = W1[j] + excl(scan88)
    for (int j = threadIdx.x; j < L1N; j += blockDim.x) {
        int b = j >> 4;
        s1[j] = __fadd_rn(s1[j], b ? s2[b-1] : 0.0f);
    }
    __syncthreads();
    // scan22500[j] = W0[j] + excl(scan1407)  -> g_P
    for (int j = threadIdx.x; j < NCHUNK; j += blockDim.x) {
        int b = j >> 4;
        g_P[row][j] = __fadd_rn(s0[j], b ? s1[b-1] : 0.0f);
    }
}

// ---------------------------------------------------------------------------
// K3: per leaf tile: SEQUENTIAL in-tile scan + block prefix -> rad ->
// sawtooth -> impulse (with circular roll).
// ---------------------------------------------------------------------------
__global__ void k3_impulse(const float* __restrict__ f0) {
    __shared__ float sf0[T_FRAMES];
    int row = blockIdx.y;
    for (int j = threadIdx.x; j < T_FRAMES; j += blockDim.x)
        sf0[j] = f0[row * T_FRAMES + j];
    __syncthreads();

    int c = blockIdx.x * blockDim.x + threadIdx.x;
    if (c >= NCHUNK) return;
    int base = c * 16;

    float e0[16];
#pragma unroll
    for (int j = 0; j < 16; j++) e0[j] = vval(sf0, base + j);
    float h[16];
    seq16(e0, h);

    // rad[16c+r] = inner[c][r] + excl[c]; block 0 adds the literal 0 pad.
    float P = (c == 0) ? 0.0f : g_P[row][c - 1];

    // previous sample's rad (circular roll): rad[16b+15] = S0[b] + excl[b]
    float pr;
    if (c == 0)      pr = __fadd_rn(g_E4[row][NCHUNK-1], g_P[row][NCHUNK-2]);
    else if (c == 1) pr = __fadd_rn(g_E4[row][0], 0.0f);
    else             pr = __fadd_rn(g_E4[row][c-1], g_P[row][c-2]);
    float prev_saw = jmod1(pr);

#pragma unroll
    for (int j = 0; j < 16; j++) {
        float s = jmod1(__fadd_rn(h[j], P));
        g_imp[row][base + j] = __fadd_rn(s, -prev_saw);
        prev_saw = s;
    }
}

// ---------------------------------------------------------------------------
// K4: 1003-tap FIR (fp32, smem-tiled sliding window) + voiced select.
// ---------------------------------------------------------------------------
#define TILE 2048
#define CTH  256

__global__ __launch_bounds__(CTH) void k4_conv(const float* __restrict__ f0,
                                               const float* __restrict__ noise,
                                               const float* __restrict__ kern,
                                               float* __restrict__ out) {
    __shared__ float sw[1016];
    __shared__ float simp[TILE + 1024];
    __shared__ float sf0[T_FRAMES];

    int row  = blockIdx.y;
    int base = blockIdx.x * TILE;

    for (int j = threadIdx.x; j < 1016; j += CTH)
        sw[j] = (j < KSIZE) ? kern[j] : 0.0f;
    for (int j = threadIdx.x; j < T_FRAMES; j += CTH)
        sf0[j] = f0[row * T_FRAMES + j];
    for (int j = threadIdx.x; j < TILE + 1024; j += CTH) {
        int g = base + j;
        simp[j] = (g < L_SAMPLES) ? g_imp[row][g] : 0.0f;
    }
    __syncthreads();

    int o = threadIdx.x * 8;
    float acc[8], r[8];
#pragma unroll
    for (int u = 0; u < 8; u++) { acc[u] = 0.0f; r[u] = simp[o + u]; }

    for (int k = 0; k < 1008; k += 8) {
#pragma unroll
        for (int kk = 0; kk < 8; kk++) {
            float wv = sw[k + kk];
#pragma unroll
            for (int u = 0; u < 8; u++)
                acc[u] = __fmaf_rn(r[(kk + u) & 7], wv, acc[u]);
            r[kk & 7] = simp[o + k + kk + 8];
        }
    }

#pragma unroll
    for (int u = 0; u < 8; u++) {
        int g = base + o + u;
        if (g < L_SAMPLES) {
            float fup = f0_interp(sf0, g);
            float res = (fup >= 20.0f) ? acc[u] : noise[row * L_SAMPLES + g];
            out[row * L_SAMPLES + g] = res;
        }
    }
}

// ---------------------------------------------------------------------------
extern "C" void kernel_launch(void* const* d_in, const int* in_sizes, int n_in,
                              void* d_out, int out_size) {
    const float* f0    = (const float*)d_in[0];
    const float* noise = (const float*)d_in[1];
    const float* kern  = (const float*)d_in[2];
    float* out = (float*)d_out;

    dim3 gchunk((NCHUNK + 255) / 256, N_BATCH);
    k1_up<<<gchunk, 256>>>(f0);

    int smem_bytes = (22512 + L1P + L2P + 8) * 4;
    cudaFuncSetAttribute(k2_mid, cudaFuncAttributeMaxDynamicSharedMemorySize, smem_bytes);
    k2_mid<<<N_BATCH, 1024, smem_bytes>>>();

    k3_impulse<<<gchunk, 256>>>(f0);

    dim3 gconv((L_SAMPLES + TILE - 1) / TILE, N_BATCH);
    k4_conv<<<gconv, CTH>>>(f0, noise, kern, out);
}

// round 10
// speedup vs baseline: 2.3304x; 2.3304x over previous
#include <cuda_runtime.h>

#define L_SAMPLES 360000
#define N_BATCH   32
#define T_FRAMES  750
#define KSIZE     1003
#define NCHUNK    22500   // number of 16-sample leaf tiles per row

// Recursion sizes for the ReduceWindowRewriter structure (base 16):
#define L1N 1407
#define L1P 1408
#define L2N 88
#define L2P 96
#define L3N 6

// Leaf config (R, R): both constant divides strength-reduced to multiplies
// by the correctly-rounded fp32 reciprocals.
#define RCP_SR   (1.0f / 24000.0f)
#define RCP_FS   (1.0f / 480.0f)

// Scratch (static device arrays — no runtime allocation)
__device__ float g_E4[N_BATCH][NCHUNK];        // leaf-tile sums S0 (sequential folds)
__device__ float g_P [N_BATCH][NCHUNK];        // inclusive scan of S0 (block prefixes)
__device__ float g_imp[N_BATCH][L_SAMPLES];    // impulse train

// ---------------------------------------------------------------------------
// Bitwise emulation of the reference elementwise math. (FROZEN — verified)
// ---------------------------------------------------------------------------
__device__ __forceinline__ float f0_interp(const float* __restrict__ f0row, int i) {
    float x = __fmul_rn(__fadd_rn((float)i, 0.5f), RCP_FS);
    x = __fadd_rn(x, -0.5f);
    x = fminf(fmaxf(x, 0.0f), 749.0f);     // jnp.clip
    float fi0 = floorf(x);
    int i0 = (int)fi0;
    int i1 = i0 + 1; if (i1 > 749) i1 = 749;
    float w = __fadd_rn(x, -fi0);
    float a = __fmul_rn(f0row[i0], __fadd_rn(1.0f, -w));
    float b = __fmul_rn(f0row[i1], w);
    return __fadd_rn(a, b);
}

__device__ __forceinline__ float vval(const float* __restrict__ f0row, int i) {
    return __fmul_rn(-f0_interp(f0row, i), RCP_SR);   // -f0_up * (1/24000)
}

// jnp.mod(x, 1.0)
__device__ __forceinline__ float jmod1(float r) {
    float t = fmodf(r, 1.0f);
    if (t != 0.0f && t < 0.0f) t = __fadd_rn(t, 1.0f);
    return t;
}

// Naive reduce-window scan: sequential left fold from init 0.
__device__ __forceinline__ void seq16(const float* __restrict__ in, float* __restrict__ out) {
    float acc = 0.0f;
#pragma unroll
    for (int i = 0; i < 16; i++) { acc = __fadd_rn(acc, in[i]); out[i] = acc; }
}

// ---------------------------------------------------------------------------
// K1: per-tile (16 samples) SEQUENTIAL sums -> S0. (FROZEN)
// ---------------------------------------------------------------------------
__global__ void k1_up(const float* __restrict__ f0) {
    __shared__ float sf0[T_FRAMES];
    int row = blockIdx.y;
    for (int j = threadIdx.x; j < T_FRAMES; j += blockDim.x)
        sf0[j] = f0[row * T_FRAMES + j];
    __syncthreads();

    int c = blockIdx.x * blockDim.x + threadIdx.x;
    if (c >= NCHUNK) return;
    int base = c * 16;

    float acc = 0.0f;
#pragma unroll
    for (int j = 0; j < 16; j++) acc = __fadd_rn(acc, vval(sf0, base + j));
    g_E4[row][c] = acc;
}

// ---------------------------------------------------------------------------
// K2: ReduceWindowRewriter recursion on S0 -> g_P. (FROZEN)
// ---------------------------------------------------------------------------
__global__ void k2_mid() {
    extern __shared__ float sm[];
    float* s0 = sm;                 // 22512 (W0 in place)
    float* s1 = sm + 22512;         // 1408  (W1 in place)
    float* s2 = s1 + L1P;           // 96    (W2 in place)
    float* s3 = s2 + L2P;           // 6
    int row = blockIdx.x;

    for (int i = threadIdx.x; i < 22512; i += blockDim.x)
        s0[i] = (i < NCHUNK) ? g_E4[row][i] : 0.0f;
    __syncthreads();

    for (int b = threadIdx.x; b < L1N; b += blockDim.x) {
        float w[16];
        seq16(s0 + 16*b, w);
#pragma unroll
        for (int i = 0; i < 16; i++) s0[16*b + i] = w[i];
        s1[b] = w[15];
    }
    if (threadIdx.x == 0) s1[L1N] = 0.0f;   // pad 1407 -> 1408
    __syncthreads();

    for (int b = threadIdx.x; b < L2N; b += blockDim.x) {
        float w[16];
        seq16(s1 + 16*b, w);
#pragma unroll
        for (int i = 0; i < 16; i++) s1[16*b + i] = w[i];
        s2[b] = w[15];
    }
    for (int i = L2N + threadIdx.x; i < L2P; i += blockDim.x) s2[i] = 0.0f;  // pad 88 -> 96
    __syncthreads();

    for (int b = threadIdx.x; b < L3N; b += blockDim.x) {
        float w[16];
        seq16(s2 + 16*b, w);
#pragma unroll
        for (int i = 0; i < 16; i++) s2[16*b + i] = w[i];
        s3[b] = w[15];
    }
    __syncthreads();

    if (threadIdx.x == 0) {
        float acc = 0.0f;
        for (int i = 0; i < L3N; i++) { acc = __fadd_rn(acc, s3[i]); s3[i] = acc; }
    }
    __syncthreads();

    for (int j = threadIdx.x; j < L2N; j += blockDim.x) {
        int b = j >> 4;
        s2[j] = __fadd_rn(s2[j], b ? s3[b-1] : 0.0f);
    }
    __syncthreads();
    for (int j = threadIdx.x; j < L1N; j += blockDim.x) {
        int b = j >> 4;
        s1[j] = __fadd_rn(s1[j], b ? s2[b-1] : 0.0f);
    }
    __syncthreads();
    for (int j = threadIdx.x; j < NCHUNK; j += blockDim.x) {
        int b = j >> 4;
        g_P[row][j] = __fadd_rn(s0[j], b ? s1[b-1] : 0.0f);
    }
}

// ---------------------------------------------------------------------------
// K3: per leaf tile: sequential in-tile scan + block prefix -> impulse. (FROZEN)
// ---------------------------------------------------------------------------
__global__ void k3_impulse(const float* __restrict__ f0) {
    __shared__ float sf0[T_FRAMES];
    int row = blockIdx.y;
    for (int j = threadIdx.x; j < T_FRAMES; j += blockDim.x)
        sf0[j] = f0[row * T_FRAMES + j];
    __syncthreads();

    int c = blockIdx.x * blockDim.x + threadIdx.x;
    if (c >= NCHUNK) return;
    int base = c * 16;

    float e0[16];
#pragma unroll
    for (int j = 0; j < 16; j++) e0[j] = vval(sf0, base + j);
    float h[16];
    seq16(e0, h);

    float P = (c == 0) ? 0.0f : g_P[row][c - 1];

    float pr;
    if (c == 0)      pr = __fadd_rn(g_E4[row][NCHUNK-1], g_P[row][NCHUNK-2]);
    else if (c == 1) pr = __fadd_rn(g_E4[row][0], 0.0f);
    else             pr = __fadd_rn(g_E4[row][c-1], g_P[row][c-2]);
    float prev_saw = jmod1(pr);

#pragma unroll
    for (int j = 0; j < 16; j++) {
        float s = jmod1(__fadd_rn(h[j], P));
        g_imp[row][base + j] = __fadd_rn(s, -prev_saw);
        prev_saw = s;
    }
}

// ---------------------------------------------------------------------------
// K4 (REWRITTEN): 1003-tap FIR, conflict-free float4 sliding window.
// Each thread computes 4 contiguous outputs at o = 4*tid; window advances by
// float4 loads s4[tid + kq] whose lane addresses are 16B-consecutive across
// the warp (zero bank conflicts). Weights read as broadcast float4.
// ---------------------------------------------------------------------------
#define CTH    256
#define OTILE  1024              // outputs per block
#define SMW    2048              // smem window floats (OTILE + 1008 + pad)
#define NW4    252               // 1008 weights as float4 count

__global__ __launch_bounds__(CTH) void k4_conv(const float* __restrict__ f0,
                                               const float* __restrict__ noise,
                                               const float* __restrict__ kern,
                                               float* __restrict__ out) {
    __shared__ float4 s4[SMW / 4];          // 512 float4 = 8KB
    __shared__ float4 w4s[NW4 + 2];         // 1008 weights (+pad)
    __shared__ float  sf0[T_FRAMES];

    int row  = blockIdx.y;
    int base = blockIdx.x * OTILE;

    float* sw   = (float*)w4s;
    float* simp = (float*)s4;

    for (int j = threadIdx.x; j < (NW4 + 2) * 4; j += CTH)
        sw[j] = (j < KSIZE) ? kern[j] : 0.0f;
    for (int j = threadIdx.x; j < T_FRAMES; j += CTH)
        sf0[j] = f0[row * T_FRAMES + j];
    for (int j = threadIdx.x; j < SMW; j += CTH) {
        int g = base + j;
        simp[j] = (g < L_SAMPLES) ? g_imp[row][g] : 0.0f;
    }
    __syncthreads();

    const int t = threadIdx.x;
    float a0 = 0.0f, a1 = 0.0f, a2 = 0.0f, a3 = 0.0f;
    float4 A = s4[t];
    float4 B = s4[t + 1];

#pragma unroll 2
    for (int kq = 0; kq < NW4; kq += 2) {
        // taps 4*kq .. 4*kq+3 use window f[0..6] = A.xyzw, B.xyz
        float4 C  = s4[t + kq + 2];
        float4 wa = w4s[kq];
        a0 = fmaf(A.x, wa.x, a0); a1 = fmaf(A.y, wa.x, a1);
        a2 = fmaf(A.z, wa.x, a2); a3 = fmaf(A.w, wa.x, a3);
        a0 = fmaf(A.y, wa.y, a0); a1 = fmaf(A.z, wa.y, a1);
        a2 = fmaf(A.w, wa.y, a2); a3 = fmaf(B.x, wa.y, a3);
        a0 = fmaf(A.z, wa.z, a0); a1 = fmaf(A.w, wa.z, a1);
        a2 = fmaf(B.x, wa.z, a2); a3 = fmaf(B.y, wa.z, a3);
        a0 = fmaf(A.w, wa.w, a0); a1 = fmaf(B.x, wa.w, a1);
        a2 = fmaf(B.y, wa.w, a2); a3 = fmaf(B.z, wa.w, a3);

        // taps 4*kq+4 .. 4*kq+7 use window B.xyzw, C.xyz
        float4 D  = s4[t + kq + 3];
        float4 wb = w4s[kq + 1];
        a0 = fmaf(B.x, wb.x, a0); a1 = fmaf(B.y, wb.x, a1);
        a2 = fmaf(B.z, wb.x, a2); a3 = fmaf(B.w, wb.x, a3);
        a0 = fmaf(B.y, wb.y, a0); a1 = fmaf(B.z, wb.y, a1);
        a2 = fmaf(B.w, wb.y, a2); a3 = fmaf(C.x, wb.y, a3);
        a0 = fmaf(B.z, wb.z, a0); a1 = fmaf(B.w, wb.z, a1);
        a2 = fmaf(C.x, wb.z, a2); a3 = fmaf(C.y, wb.z, a3);
        a0 = fmaf(B.w, wb.w, a0); a1 = fmaf(C.x, wb.w, a1);
        a2 = fmaf(C.y, wb.w, a2); a3 = fmaf(C.z, wb.w, a3);

        A = C; B = D;
    }

    float acc[4] = {a0, a1, a2, a3};
#pragma unroll
    for (int u = 0; u < 4; u++) {
        int g = base + 4 * t + u;
        if (g < L_SAMPLES) {
            float fup = f0_interp(sf0, g);
            float res = (fup >= 20.0f) ? acc[u] : noise[row * L_SAMPLES + g];
            out[row * L_SAMPLES + g] = res;
        }
    }
}

// ---------------------------------------------------------------------------
extern "C" void kernel_launch(void* const* d_in, const int* in_sizes, int n_in,
                              void* d_out, int out_size) {
    const float* f0    = (const float*)d_in[0];
    const float* noise = (const float*)d_in[1];
    const float* kern  = (const float*)d_in[2];
    float* out = (float*)d_out;

    dim3 gchunk((NCHUNK + 255) / 256, N_BATCH);
    k1_up<<<gchunk, 256>>>(f0);

    int smem_bytes = (22512 + L1P + L2P + 8) * 4;
    cudaFuncSetAttribute(k2_mid, cudaFuncAttributeMaxDynamicSharedMemorySize, smem_bytes);
    k2_mid<<<N_BATCH, 1024, smem_bytes>>>();

    k3_impulse<<<gchunk, 256>>>(f0);

    dim3 gconv((L_SAMPLES + OTILE - 1) / OTILE, N_BATCH);
    k4_conv<<<gconv, CTH>>>(f0, noise, kern, out);
}

// round 11
// speedup vs baseline: 2.9009x; 1.2448x over previous
#include <cuda_runtime.h>

#define L_SAMPLES 360000
#define N_BATCH   32
#define T_FRAMES  750
#define KSIZE     1003
#define NCHUNK    22500   // number of 16-sample leaf tiles per row

// Recursion sizes for the ReduceWindowRewriter structure (base 16):
#define L1N 1407
#define L1P 1408
#define L2N 88
#define L2P 96
#define L3N 6

// Leaf config (R, R)
#define RCP_SR   (1.0f / 24000.0f)
#define RCP_FS   (1.0f / 480.0f)

// Scratch (static device arrays — no runtime allocation)
__device__ float g_E4[N_BATCH][NCHUNK];
__device__ float g_P [N_BATCH][NCHUNK];
__device__ float g_imp[N_BATCH][L_SAMPLES];

// ---------------------------------------------------------------------------
// Bitwise emulation of the reference elementwise math. (FROZEN — verified)
// ---------------------------------------------------------------------------
__device__ __forceinline__ float f0_interp(const float* __restrict__ f0row, int i) {
    float x = __fmul_rn(__fadd_rn((float)i, 0.5f), RCP_FS);
    x = __fadd_rn(x, -0.5f);
    x = fminf(fmaxf(x, 0.0f), 749.0f);
    float fi0 = floorf(x);
    int i0 = (int)fi0;
    int i1 = i0 + 1; if (i1 > 749) i1 = 749;
    float w = __fadd_rn(x, -fi0);
    float a = __fmul_rn(f0row[i0], __fadd_rn(1.0f, -w));
    float b = __fmul_rn(f0row[i1], w);
    return __fadd_rn(a, b);
}

__device__ __forceinline__ float vval(const float* __restrict__ f0row, int i) {
    return __fmul_rn(-f0_interp(f0row, i), RCP_SR);
}

__device__ __forceinline__ float jmod1(float r) {
    float t = fmodf(r, 1.0f);
    if (t != 0.0f && t < 0.0f) t = __fadd_rn(t, 1.0f);
    return t;
}

__device__ __forceinline__ void seq16(const float* __restrict__ in, float* __restrict__ out) {
    float acc = 0.0f;
#pragma unroll
    for (int i = 0; i < 16; i++) { acc = __fadd_rn(acc, in[i]); out[i] = acc; }
}

// ---------------------------------------------------------------------------
// K1 (FROZEN)
// ---------------------------------------------------------------------------
__global__ void k1_up(const float* __restrict__ f0) {
    __shared__ float sf0[T_FRAMES];
    int row = blockIdx.y;
    for (int j = threadIdx.x; j < T_FRAMES; j += blockDim.x)
        sf0[j] = f0[row * T_FRAMES + j];
    __syncthreads();

    int c = blockIdx.x * blockDim.x + threadIdx.x;
    if (c >= NCHUNK) return;
    int base = c * 16;

    float acc = 0.0f;
#pragma unroll
    for (int j = 0; j < 16; j++) acc = __fadd_rn(acc, vval(sf0, base + j));
    g_E4[row][c] = acc;
}

// ---------------------------------------------------------------------------
// K2 (FROZEN)
// ---------------------------------------------------------------------------
__global__ void k2_mid() {
    extern __shared__ float sm[];
    float* s0 = sm;
    float* s1 = sm + 22512;
    float* s2 = s1 + L1P;
    float* s3 = s2 + L2P;
    int row = blockIdx.x;

    for (int i = threadIdx.x; i < 22512; i += blockDim.x)
        s0[i] = (i < NCHUNK) ? g_E4[row][i] : 0.0f;
    __syncthreads();

    for (int b = threadIdx.x; b < L1N; b += blockDim.x) {
        float w[16];
        seq16(s0 + 16*b, w);
#pragma unroll
        for (int i = 0; i < 16; i++) s0[16*b + i] = w[i];
        s1[b] = w[15];
    }
    if (threadIdx.x == 0) s1[L1N] = 0.0f;
    __syncthreads();

    for (int b = threadIdx.x; b < L2N; b += blockDim.x) {
        float w[16];
        seq16(s1 + 16*b, w);
#pragma unroll
        for (int i = 0; i < 16; i++) s1[16*b + i] = w[i];
        s2[b] = w[15];
    }
    for (int i = L2N + threadIdx.x; i < L2P; i += blockDim.x) s2[i] = 0.0f;
    __syncthreads();

    for (int b = threadIdx.x; b < L3N; b += blockDim.x) {
        float w[16];
        seq16(s2 + 16*b, w);
#pragma unroll
        for (int i = 0; i < 16; i++) s2[16*b + i] = w[i];
        s3[b] = w[15];
    }
    __syncthreads();

    if (threadIdx.x == 0) {
        float acc = 0.0f;
        for (int i = 0; i < L3N; i++) { acc = __fadd_rn(acc, s3[i]); s3[i] = acc; }
    }
    __syncthreads();

    for (int j = threadIdx.x; j < L2N; j += blockDim.x) {
        int b = j >> 4;
        s2[j] = __fadd_rn(s2[j], b ? s3[b-1] : 0.0f);
    }
    __syncthreads();
    for (int j = threadIdx.x; j < L1N; j += blockDim.x) {
        int b = j >> 4;
        s1[j] = __fadd_rn(s1[j], b ? s2[b-1] : 0.0f);
    }
    __syncthreads();
    for (int j = threadIdx.x; j < NCHUNK; j += blockDim.x) {
        int b = j >> 4;
        g_P[row][j] = __fadd_rn(s0[j], b ? s1[b-1] : 0.0f);
    }
}

// ---------------------------------------------------------------------------
// K3 (FROZEN)
// ---------------------------------------------------------------------------
__global__ void k3_impulse(const float* __restrict__ f0) {
    __shared__ float sf0[T_FRAMES];
    int row = blockIdx.y;
    for (int j = threadIdx.x; j < T_FRAMES; j += blockDim.x)
        sf0[j] = f0[row * T_FRAMES + j];
    __syncthreads();

    int c = blockIdx.x * blockDim.x + threadIdx.x;
    if (c >= NCHUNK) return;
    int base = c * 16;

    float e0[16];
#pragma unroll
    for (int j = 0; j < 16; j++) e0[j] = vval(sf0, base + j);
    float h[16];
    seq16(e0, h);

    float P = (c == 0) ? 0.0f : g_P[row][c - 1];

    float pr;
    if (c == 0)      pr = __fadd_rn(g_E4[row][NCHUNK-1], g_P[row][NCHUNK-2]);
    else if (c == 1) pr = __fadd_rn(g_E4[row][0], 0.0f);
    else             pr = __fadd_rn(g_E4[row][c-1], g_P[row][c-2]);
    float prev_saw = jmod1(pr);

#pragma unroll
    for (int j = 0; j < 16; j++) {
        float s = jmod1(__fadd_rn(h[j], P));
        g_imp[row][base + j] = __fadd_rn(s, -prev_saw);
        prev_saw = s;
    }
}

// ---------------------------------------------------------------------------
// K4: 1003-tap FIR, U=8 outputs/thread, parity-deinterleaved float4 planes.
// Window float4 index 2j -> pl0[j], 2j+1 -> pl1[j]; thread t reads pl0[t+s],
// pl1[t+s]: lane-consecutive -> conflict-free.
// ---------------------------------------------------------------------------
#define CTH    256
#define UO     8
#define OTILE  2048              // 256 threads * 8 outputs
#define WFLT   3072              // window floats: 2048 + 1008 + pad
#define NPLANE 384               // float4 per plane (768 total float4)
#define NW4    254               // 1016 weight floats as float4

__global__ __launch_bounds__(CTH) void k4_conv(const float* __restrict__ f0,
                                               const float* __restrict__ noise,
                                               const float* __restrict__ kern,
                                               float* __restrict__ out) {
    __shared__ float4 pl0[NPLANE + 2];
    __shared__ float4 pl1[NPLANE + 2];
    __shared__ float4 w4s[NW4];
    __shared__ float  sf0[T_FRAMES];

    int row  = blockIdx.y;
    int base = blockIdx.x * OTILE;

    float* sw = (float*)w4s;
    for (int j = threadIdx.x; j < NW4 * 4; j += CTH)
        sw[j] = (j < KSIZE) ? kern[j] : 0.0f;
    for (int j = threadIdx.x; j < T_FRAMES; j += CTH)
        sf0[j] = f0[row * T_FRAMES + j];

    // Fill window planes: logical float4 jf covers floats [4jf, 4jf+3].
    const float* impRow = g_imp[row];
    for (int jf = threadIdx.x; jf < 2 * NPLANE; jf += CTH) {
        int g = base + 4 * jf;
        float4 v;
        if (g + 3 < L_SAMPLES) {
            v = *reinterpret_cast<const float4*>(impRow + g);
        } else {
            v.x = (g + 0 < L_SAMPLES) ? impRow[g + 0] : 0.0f;
            v.y = (g + 1 < L_SAMPLES) ? impRow[g + 1] : 0.0f;
            v.z = (g + 2 < L_SAMPLES) ? impRow[g + 2] : 0.0f;
            v.w = (g + 3 < L_SAMPLES) ? impRow[g + 3] : 0.0f;
        }
        if (jf & 1) pl1[jf >> 1] = v;
        else        pl0[jf >> 1] = v;
    }
    __syncthreads();

    const int t = threadIdx.x;
    float acc[UO];
#pragma unroll
    for (int u = 0; u < UO; u++) acc[u] = 0.0f;

    // window regs f[0..15] = float4 {pl0[t+s], pl1[t+s], pl0[t+s+1], pl1[t+s+1]}
    float4 A = pl0[t];
    float4 Bq = pl1[t];
    float4 Cq = pl0[t + 1];
    float4 Dq = pl1[t + 1];

#pragma unroll 2
    for (int it = 0; it < 126; ++it) {
        float4 E = pl0[t + it + 2];
        float4 F = pl1[t + it + 2];
        float4 wa = w4s[2 * it];
        float4 wb = w4s[2 * it + 1];

        float f[16];
        f[0]=A.x;  f[1]=A.y;  f[2]=A.z;  f[3]=A.w;
        f[4]=Bq.x; f[5]=Bq.y; f[6]=Bq.z; f[7]=Bq.w;
        f[8]=Cq.x; f[9]=Cq.y; f[10]=Cq.z;f[11]=Cq.w;
        f[12]=Dq.x;f[13]=Dq.y;f[14]=Dq.z;f[15]=Dq.w;

        float wv;
#pragma unroll
        for (int kk = 0; kk < 8; kk++) {
            wv = (kk < 4) ? ((kk==0)?wa.x:(kk==1)?wa.y:(kk==2)?wa.z:wa.w)
                          : ((kk==4)?wb.x:(kk==5)?wb.y:(kk==6)?wb.z:wb.w);
#pragma unroll
            for (int u = 0; u < UO; u++)
                acc[u] = fmaf(f[u + kk], wv, acc[u]);
        }

        A = Cq; Bq = Dq; Cq = E; Dq = F;
    }

    // Epilogue: voiced select + store.
    int g0 = base + UO * t;
#pragma unroll
    for (int u = 0; u < UO; u++) {
        int g = g0 + u;
        if (g < L_SAMPLES) {
            float fup = f0_interp(sf0, g);
            float res = (fup >= 20.0f) ? acc[u] : noise[row * L_SAMPLES + g];
            out[row * L_SAMPLES + g] = res;
        }
    }
}

// ---------------------------------------------------------------------------
extern "C" void kernel_launch(void* const* d_in, const int* in_sizes, int n_in,
                              void* d_out, int out_size) {
    const float* f0    = (const float*)d_in[0];
    const float* noise = (const float*)d_in[1];
    const float* kern  = (const float*)d_in[2];
    float* out = (float*)d_out;

    dim3 gchunk((NCHUNK + 255) / 256, N_BATCH);
    k1_up<<<gchunk, 256>>>(f0);

    int smem_bytes = (22512 + L1P + L2P + 8) * 4;
    cudaFuncSetAttribute(k2_mid, cudaFuncAttributeMaxDynamicSharedMemorySize, smem_bytes);
    k2_mid<<<N_BATCH, 1024, smem_bytes>>>();

    k3_impulse<<<gchunk, 256>>>(f0);

    dim3 gconv((L_SAMPLES + OTILE - 1) / OTILE, N_BATCH);
    k4_conv<<<gconv, CTH>>>(f0, noise, kern, out);
}